// round 13
// baseline (speedup 1.0000x reference)
#include <cuda_runtime.h>
#include <cstdint>
#include <cstddef>

#define B_   16
#define CI_  32
#define HH   224
#define WW   224
#define CO_  32
#define OH_  222
#define OW_  222

// g_xh: bf16-hi per pixel, 16 words: uint4[t] = {h_t, h_{t+4}, h_{8+t}, h_{12+t}}
//       h_p = packed bf16x2 (truncated) of ci {2p, 2p+1} (low half = ci 2p)
// g_xq: fp8 per pixel, 16 words: uint4[t] = {xh8[4t..4t+3], xh8[16+4t..], xl8[4t..], xl8[16+4t..]}
//       xh8 = e4m3(trunc-bf16(x)); xl8 = e4m3((x - xh)*512); k index = ci
static __device__ __align__(16) unsigned g_xh[(size_t)B_ * HH * WW * 16];
static __device__ __align__(16) unsigned g_xq[(size_t)B_ * HH * WW * 16];
// per (tap*32+co): g_wh like g_xh; g_wq uint4[t] = {wl8[4t..], wl8[16+4t..], wh8[4t..], wh8[16+4t..]}
static __device__ __align__(16) unsigned g_wh[9 * CO_ * 16];
static __device__ __align__(16) unsigned g_wq[9 * CO_ * 16];

#define THREADS 256
#define XT 2
#define YT 111
#define TROWS 4
#define TCOLS 136
#define SA_PLANE (TROWS * TCOLS * 16)       // 8704 words (per plane: bf16-hi / fp8)
#define SB_PLANE (9 * CO_ * 16)             // 4608 words
#define SMEM_WORDS (2 * SA_PLANE + 2 * SB_PLANE)   // 26624
#define SMEM_BYTES (SMEM_WORDS * 4)                // 106496 -> 2 CTAs/SM

__device__ __forceinline__ unsigned pack_hi_trunc(unsigned u0, unsigned u1) {
    unsigned d;   // {lo16: u0>>16, hi16: u1>>16}
    asm("prmt.b32 %0, %1, %2, 0x7632;" : "=r"(d) : "r"(u0), "r"(u1));
    return d;
}
__device__ __forceinline__ unsigned pack_e4m3x4(float f0, float f1, float f2, float f3) {
    unsigned short h0, h1;   // cvt e4m3x2: high byte <- first operand
    asm("cvt.rn.satfinite.e4m3x2.f32 %0, %1, %2;" : "=h"(h0) : "f"(f1), "f"(f0));
    asm("cvt.rn.satfinite.e4m3x2.f32 %0, %1, %2;" : "=h"(h1) : "f"(f3), "f"(f2));
    return (unsigned)h0 | ((unsigned)h1 << 16);
}
__device__ __forceinline__ void mma_bf16(float* c, unsigned a0, unsigned a1,
                                         unsigned a2, unsigned a3,
                                         unsigned b0, unsigned b1) {
    asm volatile(
        "mma.sync.aligned.m16n8k16.row.col.f32.bf16.bf16.f32 "
        "{%0,%1,%2,%3}, {%4,%5,%6,%7}, {%8,%9}, {%0,%1,%2,%3};"
        : "+f"(c[0]), "+f"(c[1]), "+f"(c[2]), "+f"(c[3])
        : "r"(a0), "r"(a1), "r"(a2), "r"(a3), "r"(b0), "r"(b1));
}
__device__ __forceinline__ void mma_fp8(float* c, unsigned a0, unsigned a1,
                                        unsigned a2, unsigned a3,
                                        unsigned b0, unsigned b1) {
    asm volatile(
        "mma.sync.aligned.m16n8k32.row.col.f32.e4m3.e4m3.f32 "
        "{%0,%1,%2,%3}, {%4,%5,%6,%7}, {%8,%9}, {%0,%1,%2,%3};"
        : "+f"(c[0]), "+f"(c[1]), "+f"(c[2]), "+f"(c[3])
        : "r"(a0), "r"(a1), "r"(a2), "r"(a3), "r"(b0), "r"(b1));
}
__device__ __forceinline__ void cp16(unsigned dst, const void* src, int nbytes) {
    asm volatile("cp.async.cg.shared.global [%0], [%1], 16, %2;"
                 :: "r"(dst), "l"(src), "r"(nbytes) : "memory");
}
#define CP_COMMIT() asm volatile("cp.async.commit_group;" ::: "memory")
#define CP_WAIT1()  asm volatile("cp.async.wait_group 1;" ::: "memory")
#define CP_WAIT0()  asm volatile("cp.async.wait_group 0;" ::: "memory")

// convert 32 ci values at one source location into the two 16-word cells
__device__ __forceinline__ void convert32(const float* src, size_t stride,
                                          uint4* dHi, uint4* dQ, int wIsB) {
    unsigned hw[16], qh[8], ql[8];
    #pragma unroll
    for (int j = 0; j < 8; ++j) {
        float f0 = __ldg(src + (size_t)(4 * j + 0) * stride);
        float f1 = __ldg(src + (size_t)(4 * j + 1) * stride);
        float f2 = __ldg(src + (size_t)(4 * j + 2) * stride);
        float f3 = __ldg(src + (size_t)(4 * j + 3) * stride);
        unsigned u0 = __float_as_uint(f0), u1 = __float_as_uint(f1);
        unsigned u2 = __float_as_uint(f2), u3 = __float_as_uint(f3);
        hw[2 * j]     = pack_hi_trunc(u0, u1);
        hw[2 * j + 1] = pack_hi_trunc(u2, u3);
        float h0 = __uint_as_float(u0 & 0xffff0000u);
        float h1 = __uint_as_float(u1 & 0xffff0000u);
        float h2 = __uint_as_float(u2 & 0xffff0000u);
        float h3 = __uint_as_float(u3 & 0xffff0000u);
        qh[j] = pack_e4m3x4(h0, h1, h2, h3);
        ql[j] = pack_e4m3x4((f0 - h0) * 512.f, (f1 - h1) * 512.f,
                            (f2 - h2) * 512.f, (f3 - h3) * 512.f);
    }
    #pragma unroll
    for (int t = 0; t < 4; ++t) {
        dHi[t] = make_uint4(hw[t], hw[t + 4], hw[8 + t], hw[12 + t]);
        dQ[t]  = wIsB ? make_uint4(ql[t], ql[t + 4], qh[t], qh[t + 4])   // B: lo in .x/.y
                      : make_uint4(qh[t], qh[t + 4], ql[t], ql[t + 4]);  // A: hi in .x/.y
    }
}

// ---- pre-pass ----
#define XBLOCKS ((B_ * HH * 7 * 32) / 256)     // 3136
__global__ void __launch_bounds__(256) cvt_xw(const float* __restrict__ x,
                                              const float* __restrict__ w) {
    if (blockIdx.x == XBLOCKS) {               // weights: r = tap*32 + co
        for (int r = threadIdx.x; r < 288; r += 256) {
            const int tap = r >> 5, co = r & 31;
            // w[co][ci][tap]: ci-stride = 9 floats
            convert32(w + co * 288 + tap, 9,
                      (uint4*)(g_wh + (size_t)r * 16),
                      (uint4*)(g_wq + (size_t)r * 16), 1);
        }
        return;
    }
    const int lane = threadIdx.x & 31;
    const int W    = (blockIdx.x * 256 + threadIdx.x) >> 5;
    const int wb   = W % 7;
    const int h    = (W / 7) % HH;
    const int b    = W / (7 * HH);
    const int iw   = wb * 32 + lane;
    const size_t px = ((size_t)b * HH + h) * WW + iw;
    convert32(x + (size_t)b * CI_ * HH * WW + (size_t)h * WW + iw, (size_t)HH * WW,
              (uint4*)(g_xh + px * 16), (uint4*)(g_xq + px * 16), 0);
}

// hh pass: 9 taps x 2ch x 8 = 144 bf16 MMAs per warp
__device__ __forceinline__ void compute_hh(const unsigned* __restrict__ sA,
                                           const unsigned* __restrict__ sB,
                                           float acc[2][4][4],
                                           int orow, int mq, int g, int t) {
    #pragma unroll
    for (int ky = 0; ky < 3; ++ky) {
        #pragma unroll
        for (int kx = 0; kx < 3; ++kx) {
            const unsigned* bp = sB + (((ky * 3 + kx) * 32) + g) * 16 + t * 4;
            uint4 bf[4];
            #pragma unroll
            for (int nt = 0; nt < 4; ++nt)
                bf[nt] = *(const uint4*)(bp + nt * (8 * 16));
            const unsigned* ap = sA + (((orow + ky) * TCOLS + mq * 32 + kx + g)) * 16 + t * 4;
            #pragma unroll
            for (int mt = 0; mt < 2; ++mt) {
                uint4 aL = *(const uint4*)(ap + mt * (16 * 16));
                uint4 aH = *(const uint4*)(ap + (mt * 16 + 8) * 16);
                #pragma unroll
                for (int nt = 0; nt < 4; ++nt) {
                    mma_bf16(acc[mt][nt], aL.x, aH.x, aL.y, aH.y, bf[nt].x, bf[nt].y); // ch0
                    mma_bf16(acc[mt][nt], aL.z, aH.z, aL.w, aH.w, bf[nt].z, bf[nt].w); // ch1
                }
            }
        }
    }
}

// cross pass: 9 taps x 2 terms x 8 = 144 fp8 k32 MMAs per warp (k = all 32 ci)
__device__ __forceinline__ void compute_cross(const unsigned* __restrict__ sA,
                                              const unsigned* __restrict__ sB,
                                              float acc[2][4][4],
                                              int orow, int mq, int g, int t) {
    #pragma unroll
    for (int ky = 0; ky < 3; ++ky) {
        #pragma unroll
        for (int kx = 0; kx < 3; ++kx) {
            const unsigned* bp = sB + (((ky * 3 + kx) * 32) + g) * 16 + t * 4;
            uint4 bf[4];
            #pragma unroll
            for (int nt = 0; nt < 4; ++nt)
                bf[nt] = *(const uint4*)(bp + nt * (8 * 16));
            const unsigned* ap = sA + (((orow + ky) * TCOLS + mq * 32 + kx + g)) * 16 + t * 4;
            #pragma unroll
            for (int mt = 0; mt < 2; ++mt) {
                uint4 aL = *(const uint4*)(ap + mt * (16 * 16));
                uint4 aH = *(const uint4*)(ap + (mt * 16 + 8) * 16);
                #pragma unroll
                for (int nt = 0; nt < 4; ++nt) {
                    // term1: xh * wl_s ; term2: xl_s * wh   (both scaled x512)
                    mma_fp8(acc[mt][nt], aL.x, aH.x, aL.y, aH.y, bf[nt].x, bf[nt].y);
                    mma_fp8(acc[mt][nt], aL.z, aH.z, aL.w, aH.w, bf[nt].z, bf[nt].w);
                }
            }
        }
    }
}

// ---- main ----
__global__ void __launch_bounds__(THREADS, 2)
conv3x3_mma(const float* __restrict__ bias, float* __restrict__ out) {
    extern __shared__ unsigned smw[];
    unsigned* sAh = smw;
    unsigned* sAq = smw + SA_PLANE;
    unsigned* sBh = smw + 2 * SA_PLANE;
    unsigned* sBq = sBh + SB_PLANE;
    const unsigned aAh = (unsigned)__cvta_generic_to_shared(sAh);
    const unsigned aAq = (unsigned)__cvta_generic_to_shared(sAq);
    const unsigned aBh = (unsigned)__cvta_generic_to_shared(sBh);
    const unsigned aBq = (unsigned)__cvta_generic_to_shared(sBq);

    const int tid = threadIdx.x;
    const int blk = blockIdx.x;
    const int bx  = blk & 1;
    const int by  = (blk >> 1) % YT;
    const int b   = blk / (2 * YT);
    const int px0 = bx ? 94 : 0;
    const int oh0 = by * 2;

    // G0: both B planes + A-hi plane
    for (int i = tid; i < 288 * 4; i += THREADS) {
        int row = i >> 2, sub = i & 3;
        cp16(aBh + (unsigned)(row * 64 + sub * 16), g_wh + (size_t)row * 16 + sub * 4, 16);
        cp16(aBq + (unsigned)(row * 64 + sub * 16), g_wq + (size_t)row * 16 + sub * 4, 16);
    }
    #pragma unroll
    for (int trow = 0; trow < TROWS; ++trow) {
        const unsigned* gr = g_xh + (((size_t)b * HH + oh0 + trow) * WW) * 16;
        const unsigned dAr = aAh + (unsigned)(trow * TCOLS * 64);
        for (int i = tid; i < TCOLS * 4; i += THREADS) {
            int col = i >> 2, sub = i & 3;
            int iw  = px0 + col;
            int ok  = (iw < WW);
            cp16(dAr + (unsigned)(col * 64 + sub * 16),
                 gr + (size_t)(ok ? iw : 0) * 16 + sub * 4, ok ? 16 : 0);
        }
    }
    CP_COMMIT();
    // G1: A-fp8 plane
    #pragma unroll
    for (int trow = 0; trow < TROWS; ++trow) {
        const unsigned* gr = g_xq + (((size_t)b * HH + oh0 + trow) * WW) * 16;
        const unsigned dAr = aAq + (unsigned)(trow * TCOLS * 64);
        for (int i = tid; i < TCOLS * 4; i += THREADS) {
            int col = i >> 2, sub = i & 3;
            int iw  = px0 + col;
            int ok  = (iw < WW);
            cp16(dAr + (unsigned)(col * 64 + sub * 16),
                 gr + (size_t)(ok ? iw : 0) * 16 + sub * 4, ok ? 16 : 0);
        }
    }
    CP_COMMIT();

    const int lane = tid & 31;
    const int wid  = tid >> 5;
    const int g = lane >> 2, t = lane & 3;
    const int orow = wid & 1;
    const int mq   = wid >> 1;

    float accH[2][4][4], accC[2][4][4];
    #pragma unroll
    for (int mt = 0; mt < 2; mt++)
        #pragma unroll
        for (int nt = 0; nt < 4; nt++)
            #pragma unroll
            for (int i = 0; i < 4; i++) { accH[mt][nt][i] = 0.f; accC[mt][nt][i] = 0.f; }

    CP_WAIT1();                 // bf16-hi plane landed; fp8 plane in flight
    __syncthreads();
    compute_hh(sAh, sBh, accH, orow, mq, g, t);

    CP_WAIT0();                 // fp8 plane landed
    __syncthreads();
    compute_cross(sAq, sBq, accC, orow, mq, g, t);

    // ---- epilogue: accH + accC/512 + bias
    const float inv512 = 1.0f / 512.0f;
    const int oy = oh0 + orow;
    #pragma unroll
    for (int nt = 0; nt < 4; ++nt) {
        const int co0 = nt * 8 + t * 2;
        const float bs0 = __ldg(&bias[co0]);
        const float bs1 = __ldg(&bias[co0 + 1]);
        float* o0 = out + (((size_t)b * CO_ + co0)     * OH_ + oy) * OW_;
        float* o1 = out + (((size_t)b * CO_ + co0 + 1) * OH_ + oy) * OW_;
        #pragma unroll
        for (int mt = 0; mt < 2; ++mt) {
            const int pl = px0 + mq * 32 + mt * 16 + g;
            o0[pl]     = accH[mt][nt][0] + accC[mt][nt][0] * inv512 + bs0;
            o1[pl]     = accH[mt][nt][1] + accC[mt][nt][1] * inv512 + bs1;
            o0[pl + 8] = accH[mt][nt][2] + accC[mt][nt][2] * inv512 + bs0;
            o1[pl + 8] = accH[mt][nt][3] + accC[mt][nt][3] * inv512 + bs1;
        }
    }
}

extern "C" void kernel_launch(void* const* d_in, const int* in_sizes, int n_in,
                              void* d_out, int out_size)
{
    const float* x    = (const float*)d_in[0];
    const float* w    = (const float*)d_in[1];
    const float* bias = (const float*)d_in[2];
    float* out        = (float*)d_out;

    cvt_xw<<<XBLOCKS + 1, 256>>>(x, w);

    cudaFuncSetAttribute(conv3x3_mma,
                         cudaFuncAttributeMaxDynamicSharedMemorySize, SMEM_BYTES);
    conv3x3_mma<<<B_ * YT * XT, THREADS, SMEM_BYTES>>>(bias, out);
}

// round 14
// speedup vs baseline: 2.0455x; 2.0455x over previous
#include <cuda_runtime.h>
#include <cstdint>
#include <cstddef>

#define B_   16
#define CI_  32
#define HH   224
#define WW   224
#define CO_  32
#define OH_  222
#define OW_  222

// fp16 converted operands: per pixel 16 words (32 ci as fp16x2).
// word order: [ch*8 + 2t]   = h_{ch*8+t}     (ci pair {2p,2p+1}, low half = even ci)
//             [ch*8 + 2t+1] = h_{ch*8+t+4}
// so each plane cell (8 words) reads as uint2[t] = {h_t', h_{t+4}'} -- exact frag pairs.
static __device__ __align__(16) unsigned g_x16[(size_t)B_ * HH * WW * 16];
static __device__ __align__(16) unsigned g_w16[9 * CO_ * 16];

#define THREADS 256
#define XT 2
#define YT 111
#define TROWS 4
#define TCOLS 136
#define SA_PLANE (TROWS * TCOLS * 8)        // 4352 words per ci-half plane
#define SB_PLANE (9 * CO_ * 8)              // 2304 words
#define SMEM_WORDS (2 * SA_PLANE + 2 * SB_PLANE)   // 13312
#define SMEM_BYTES (SMEM_WORDS * 4)                // 53248 -> 3 CTAs/SM

__device__ __forceinline__ unsigned pack_f16x2(float even, float odd) {
    unsigned d;   // low half <- 'even'
    asm("cvt.rn.f16x2.f32 %0, %1, %2;" : "=r"(d) : "f"(odd), "f"(even));
    return d;
}
__device__ __forceinline__ void mma_f16(float* c, unsigned a0, unsigned a1,
                                        unsigned a2, unsigned a3,
                                        unsigned b0, unsigned b1) {
    asm volatile(
        "mma.sync.aligned.m16n8k16.row.col.f32.f16.f16.f32 "
        "{%0,%1,%2,%3}, {%4,%5,%6,%7}, {%8,%9}, {%0,%1,%2,%3};"
        : "+f"(c[0]), "+f"(c[1]), "+f"(c[2]), "+f"(c[3])
        : "r"(a0), "r"(a1), "r"(a2), "r"(a3), "r"(b0), "r"(b1));
}
__device__ __forceinline__ void cp16(unsigned dst, const void* src, int nbytes) {
    asm volatile("cp.async.cg.shared.global [%0], [%1], 16, %2;"
                 :: "r"(dst), "l"(src), "r"(nbytes) : "memory");
}
#define CP_COMMIT() asm volatile("cp.async.commit_group;" ::: "memory")
#define CP_WAIT1()  asm volatile("cp.async.wait_group 1;" ::: "memory")
#define CP_WAIT0()  asm volatile("cp.async.wait_group 0;" ::: "memory")

// convert 32 strided floats -> 16 fp16x2 words in fragment order
__device__ __forceinline__ void convert32_f16(const float* src, size_t stride, uint4* d4) {
    unsigned h[16];
    #pragma unroll
    for (int p = 0; p < 16; ++p) {
        float e = __ldg(src + (size_t)(2 * p) * stride);
        float o = __ldg(src + (size_t)(2 * p + 1) * stride);
        h[p] = pack_f16x2(e, o);
    }
    unsigned w16[16];
    #pragma unroll
    for (int ch = 0; ch < 2; ++ch)
        #pragma unroll
        for (int t = 0; t < 4; ++t) {
            w16[ch * 8 + 2 * t]     = h[ch * 8 + t];
            w16[ch * 8 + 2 * t + 1] = h[ch * 8 + t + 4];
        }
    #pragma unroll
    for (int j = 0; j < 4; ++j)
        d4[j] = make_uint4(w16[4 * j], w16[4 * j + 1], w16[4 * j + 2], w16[4 * j + 3]);
}

// ---- pre-pass ----
#define XBLOCKS ((B_ * HH * 7 * 32) / 256)     // 3136
__global__ void __launch_bounds__(256) cvt_xw(const float* __restrict__ x,
                                              const float* __restrict__ w) {
    if (blockIdx.x == XBLOCKS) {               // weights: r = tap*32 + co
        for (int r = threadIdx.x; r < 288; r += 256) {
            const int tap = r >> 5, co = r & 31;
            convert32_f16(w + co * 288 + tap, 9, (uint4*)(g_w16 + (size_t)r * 16));
        }
        return;
    }
    const int lane = threadIdx.x & 31;
    const int W    = (blockIdx.x * 256 + threadIdx.x) >> 5;
    const int wb   = W % 7;
    const int h    = (W / 7) % HH;
    const int b    = W / (7 * HH);
    const int iw   = wb * 32 + lane;
    convert32_f16(x + (size_t)b * CI_ * HH * WW + (size_t)h * WW + iw, (size_t)HH * WW,
                  (uint4*)(g_x16 + (((size_t)b * HH + h) * WW + iw) * 16));
}

// one ci-half plane: 9 taps x 8 = 72 fp16 MMAs per warp
__device__ __forceinline__ void compute_plane(const unsigned* __restrict__ sA,
                                              const unsigned* __restrict__ sB,
                                              float acc[2][4][4],
                                              int orow, int mq, int g, int t) {
    #pragma unroll
    for (int ky = 0; ky < 3; ++ky) {
        #pragma unroll
        for (int kx = 0; kx < 3; ++kx) {
            const unsigned* bp = sB + (((ky * 3 + kx) * 32) + g) * 8 + t * 2;
            uint2 bf[4];
            #pragma unroll
            for (int nt = 0; nt < 4; ++nt)
                bf[nt] = *(const uint2*)(bp + nt * 64);      // 8 rows * 8 words

            const unsigned* ap = sA + (((orow + ky) * TCOLS + mq * 32 + kx + g)) * 8 + t * 2;
            #pragma unroll
            for (int mt = 0; mt < 2; ++mt) {
                uint2 aL = *(const uint2*)(ap + mt * 128);          // row g     (16 cells * 8)
                uint2 aH = *(const uint2*)(ap + mt * 128 + 64);     // row g + 8
                #pragma unroll
                for (int nt = 0; nt < 4; ++nt)
                    mma_f16(acc[mt][nt], aL.x, aH.x, aL.y, aH.y, bf[nt].x, bf[nt].y);
            }
        }
    }
}

// ---- main ----
__global__ void __launch_bounds__(THREADS, 3)
conv3x3_mma(const float* __restrict__ bias, float* __restrict__ out) {
    extern __shared__ unsigned smw[];
    unsigned* sA0 = smw;
    unsigned* sA1 = smw + SA_PLANE;
    unsigned* sB0 = smw + 2 * SA_PLANE;
    unsigned* sB1 = sB0 + SB_PLANE;
    const unsigned aA0 = (unsigned)__cvta_generic_to_shared(sA0);
    const unsigned aA1 = (unsigned)__cvta_generic_to_shared(sA1);
    const unsigned aB0 = (unsigned)__cvta_generic_to_shared(sB0);
    const unsigned aB1 = (unsigned)__cvta_generic_to_shared(sB1);

    const int tid = threadIdx.x;
    const int blk = blockIdx.x;
    const int bx  = blk & 1;
    const int by  = (blk >> 1) % YT;
    const int b   = blk / (2 * YT);
    const int px0 = bx ? 94 : 0;
    const int oh0 = by * 2;

    // G0: both B planes + A plane 0
    for (int i = tid; i < 288 * 2; i += THREADS) {
        int row = i >> 1, sub = i & 1;
        cp16(aB0 + (unsigned)(row * 32 + sub * 16), g_w16 + (size_t)row * 16 + sub * 4, 16);
        cp16(aB1 + (unsigned)(row * 32 + sub * 16), g_w16 + (size_t)row * 16 + 8 + sub * 4, 16);
    }
    #pragma unroll
    for (int trow = 0; trow < TROWS; ++trow) {
        const unsigned* gr = g_x16 + (((size_t)b * HH + oh0 + trow) * WW) * 16;
        const unsigned dAr = aA0 + (unsigned)(trow * TCOLS * 32);
        for (int i = tid; i < TCOLS * 2; i += THREADS) {
            int col = i >> 1, sub = i & 1;
            int iw  = px0 + col;
            int ok  = (iw < WW);
            cp16(dAr + (unsigned)(col * 32 + sub * 16),
                 gr + (size_t)(ok ? iw : 0) * 16 + sub * 4, ok ? 16 : 0);
        }
    }
    CP_COMMIT();
    // G1: A plane 1
    #pragma unroll
    for (int trow = 0; trow < TROWS; ++trow) {
        const unsigned* gr = g_x16 + (((size_t)b * HH + oh0 + trow) * WW) * 16;
        const unsigned dAr = aA1 + (unsigned)(trow * TCOLS * 32);
        for (int i = tid; i < TCOLS * 2; i += THREADS) {
            int col = i >> 1, sub = i & 1;
            int iw  = px0 + col;
            int ok  = (iw < WW);
            cp16(dAr + (unsigned)(col * 32 + sub * 16),
                 gr + (size_t)(ok ? iw : 0) * 16 + 8 + sub * 4, ok ? 16 : 0);
        }
    }
    CP_COMMIT();

    const int lane = tid & 31;
    const int wid  = tid >> 5;
    const int g = lane >> 2, t = lane & 3;
    const int orow = wid & 1;
    const int mq   = wid >> 1;

    float acc[2][4][4];
    #pragma unroll
    for (int mt = 0; mt < 2; mt++)
        #pragma unroll
        for (int nt = 0; nt < 4; nt++)
            #pragma unroll
            for (int i = 0; i < 4; i++) acc[mt][nt][i] = 0.f;

    CP_WAIT1();
    __syncthreads();
    compute_plane(sA0, sB0, acc, orow, mq, g, t);

    CP_WAIT0();
    __syncthreads();
    compute_plane(sA1, sB1, acc, orow, mq, g, t);

    // ---- epilogue
    const int oy = oh0 + orow;
    #pragma unroll
    for (int nt = 0; nt < 4; ++nt) {
        const int co0 = nt * 8 + t * 2;
        const float bs0 = __ldg(&bias[co0]);
        const float bs1 = __ldg(&bias[co0 + 1]);
        float* o0 = out + (((size_t)b * CO_ + co0)     * OH_ + oy) * OW_;
        float* o1 = out + (((size_t)b * CO_ + co0 + 1) * OH_ + oy) * OW_;
        #pragma unroll
        for (int mt = 0; mt < 2; ++mt) {
            const int pl = px0 + mq * 32 + mt * 16 + g;
            o0[pl]     = acc[mt][nt][0] + bs0;
            o1[pl]     = acc[mt][nt][1] + bs1;
            o0[pl + 8] = acc[mt][nt][2] + bs0;
            o1[pl + 8] = acc[mt][nt][3] + bs1;
        }
    }
}

extern "C" void kernel_launch(void* const* d_in, const int* in_sizes, int n_in,
                              void* d_out, int out_size)
{
    const float* x    = (const float*)d_in[0];
    const float* w    = (const float*)d_in[1];
    const float* bias = (const float*)d_in[2];
    float* out        = (float*)d_out;

    cvt_xw<<<XBLOCKS + 1, 256>>>(x, w);

    cudaFuncSetAttribute(conv3x3_mma,
                         cudaFuncAttributeMaxDynamicSharedMemorySize, SMEM_BYTES);
    conv3x3_mma<<<B_ * YT * XT, THREADS, SMEM_BYTES>>>(bias, out);
}

// round 15
// speedup vs baseline: 2.1371x; 1.0448x over previous
#include <cuda_runtime.h>
#include <cstdint>
#include <cstddef>

#define B_   16
#define CI_  32
#define HH   224
#define WW   224
#define CO_  32
#define OH_  222
#define OW_  222

// fp16 operands: per pixel 16 words (32 ci as fp16x2), fragment order:
//   [ch*8 + 2t] = h_{ch*8+t},  [ch*8 + 2t+1] = h_{ch*8+t+4}
static __device__ __align__(16) unsigned g_x16[(size_t)B_ * HH * WW * 16];
static __device__ __align__(16) unsigned g_w16[9 * CO_ * 16];

#define THREADS 256
#define XT 2
#define YT 56            // ceil(222/4)
#define TROWS 6          // 4 output rows + 2 halo
#define TCOLS 136
#define SA_PLANE (TROWS * TCOLS * 8)        // 6528 words per ci-half plane
#define SB_PLANE (9 * CO_ * 8)              // 2304 words
#define SMEM_WORDS (2 * SA_PLANE + 2 * SB_PLANE)   // 17664
#define SMEM_BYTES (SMEM_WORDS * 4)                // 70656 -> 2 CTAs/SM

__device__ __forceinline__ unsigned pack_f16x2(float even, float odd) {
    unsigned d;
    asm("cvt.rn.f16x2.f32 %0, %1, %2;" : "=r"(d) : "f"(odd), "f"(even));
    return d;
}
__device__ __forceinline__ void mma_f16(float* c, unsigned a0, unsigned a1,
                                        unsigned a2, unsigned a3,
                                        unsigned b0, unsigned b1) {
    asm volatile(
        "mma.sync.aligned.m16n8k16.row.col.f32.f16.f16.f32 "
        "{%0,%1,%2,%3}, {%4,%5,%6,%7}, {%8,%9}, {%0,%1,%2,%3};"
        : "+f"(c[0]), "+f"(c[1]), "+f"(c[2]), "+f"(c[3])
        : "r"(a0), "r"(a1), "r"(a2), "r"(a3), "r"(b0), "r"(b1));
}
__device__ __forceinline__ void cp16(unsigned dst, const void* src, int nbytes) {
    asm volatile("cp.async.cg.shared.global [%0], [%1], 16, %2;"
                 :: "r"(dst), "l"(src), "r"(nbytes) : "memory");
}
#define CP_COMMIT() asm volatile("cp.async.commit_group;" ::: "memory")
#define CP_WAIT1()  asm volatile("cp.async.wait_group 1;" ::: "memory")
#define CP_WAIT0()  asm volatile("cp.async.wait_group 0;" ::: "memory")

__device__ __forceinline__ void convert32_f16(const float* src, size_t stride, uint4* d4) {
    unsigned h[16];
    #pragma unroll
    for (int p = 0; p < 16; ++p) {
        float e = __ldg(src + (size_t)(2 * p) * stride);
        float o = __ldg(src + (size_t)(2 * p + 1) * stride);
        h[p] = pack_f16x2(e, o);
    }
    unsigned w16[16];
    #pragma unroll
    for (int ch = 0; ch < 2; ++ch)
        #pragma unroll
        for (int t = 0; t < 4; ++t) {
            w16[ch * 8 + 2 * t]     = h[ch * 8 + t];
            w16[ch * 8 + 2 * t + 1] = h[ch * 8 + t + 4];
        }
    #pragma unroll
    for (int j = 0; j < 4; ++j)
        d4[j] = make_uint4(w16[4 * j], w16[4 * j + 1], w16[4 * j + 2], w16[4 * j + 3]);
}

// ---- pre-pass ----
#define XBLOCKS ((B_ * HH * 7 * 32) / 256)     // 3136
__global__ void __launch_bounds__(256) cvt_xw(const float* __restrict__ x,
                                              const float* __restrict__ w) {
    if (blockIdx.x == XBLOCKS) {
        for (int r = threadIdx.x; r < 288; r += 256) {
            const int tap = r >> 5, co = r & 31;
            convert32_f16(w + co * 288 + tap, 9, (uint4*)(g_w16 + (size_t)r * 16));
        }
        return;
    }
    const int lane = threadIdx.x & 31;
    const int W    = (blockIdx.x * 256 + threadIdx.x) >> 5;
    const int wb   = W % 7;
    const int h    = (W / 7) % HH;
    const int b    = W / (7 * HH);
    const int iw   = wb * 32 + lane;
    convert32_f16(x + (size_t)b * CI_ * HH * WW + (size_t)h * WW + iw, (size_t)HH * WW,
                  (uint4*)(g_x16 + (((size_t)b * HH + h) * WW + iw) * 16));
}

// one ci-half plane: 9 taps x 4 mt x 4 nt = 144 fp16 MMAs per warp
__device__ __forceinline__ void compute_plane(const unsigned* __restrict__ sA,
                                              const unsigned* __restrict__ sB,
                                              float acc[4][4][4],
                                              int orow, int mq, int g, int t) {
    #pragma unroll
    for (int ky = 0; ky < 3; ++ky) {
        #pragma unroll
        for (int kx = 0; kx < 3; ++kx) {
            const unsigned* bp = sB + (((ky * 3 + kx) * 32) + g) * 8 + t * 2;
            uint2 bf[4];
            #pragma unroll
            for (int nt = 0; nt < 4; ++nt)
                bf[nt] = *(const uint2*)(bp + nt * 64);

            const unsigned* ap = sA + (((orow + ky) * TCOLS + mq * 64 + kx + g)) * 8 + t * 2;
            #pragma unroll
            for (int mt = 0; mt < 4; ++mt) {
                uint2 aL = *(const uint2*)(ap + mt * 128);          // row g
                uint2 aH = *(const uint2*)(ap + mt * 128 + 64);     // row g + 8
                #pragma unroll
                for (int nt = 0; nt < 4; ++nt)
                    mma_f16(acc[mt][nt], aL.x, aH.x, aL.y, aH.y, bf[nt].x, bf[nt].y);
            }
        }
    }
}

// ---- main ----
__global__ void __launch_bounds__(THREADS, 2)
conv3x3_mma(const float* __restrict__ bias, float* __restrict__ out) {
    extern __shared__ unsigned smw[];
    unsigned* sA0 = smw;
    unsigned* sA1 = smw + SA_PLANE;
    unsigned* sB0 = smw + 2 * SA_PLANE;
    unsigned* sB1 = sB0 + SB_PLANE;
    const unsigned aA0 = (unsigned)__cvta_generic_to_shared(sA0);
    const unsigned aA1 = (unsigned)__cvta_generic_to_shared(sA1);
    const unsigned aB0 = (unsigned)__cvta_generic_to_shared(sB0);
    const unsigned aB1 = (unsigned)__cvta_generic_to_shared(sB1);

    const int tid = threadIdx.x;
    const int blk = blockIdx.x;
    const int bx  = blk & 1;
    const int by  = (blk >> 1) % YT;
    const int b   = blk / (2 * YT);
    const int px0 = bx ? 94 : 0;
    const int oh0 = by * 4;

    // G0: both B planes + A plane 0
    for (int i = tid; i < 288 * 2; i += THREADS) {
        int row = i >> 1, sub = i & 1;
        cp16(aB0 + (unsigned)(row * 32 + sub * 16), g_w16 + (size_t)row * 16 + sub * 4, 16);
        cp16(aB1 + (unsigned)(row * 32 + sub * 16), g_w16 + (size_t)row * 16 + 8 + sub * 4, 16);
    }
    #pragma unroll
    for (int trow = 0; trow < TROWS; ++trow) {
        const int ih = oh0 + trow;
        const unsigned* gr = g_x16 + (((size_t)b * HH + ih) * WW) * 16;
        const unsigned dAr = aA0 + (unsigned)(trow * TCOLS * 32);
        for (int i = tid; i < TCOLS * 2; i += THREADS) {
            int col = i >> 1, sub = i & 1;
            int iw  = px0 + col;
            int ok  = (iw < WW) && (ih < HH);
            cp16(dAr + (unsigned)(col * 32 + sub * 16),
                 gr + (size_t)(ok ? iw : 0) * 16 + sub * 4, ok ? 16 : 0);
        }
    }
    CP_COMMIT();
    // G1: A plane 1
    #pragma unroll
    for (int trow = 0; trow < TROWS; ++trow) {
        const int ih = oh0 + trow;
        const unsigned* gr = g_x16 + (((size_t)b * HH + ih) * WW) * 16;
        const unsigned dAr = aA1 + (unsigned)(trow * TCOLS * 32);
        for (int i = tid; i < TCOLS * 2; i += THREADS) {
            int col = i >> 1, sub = i & 1;
            int iw  = px0 + col;
            int ok  = (iw < WW) && (ih < HH);
            cp16(dAr + (unsigned)(col * 32 + sub * 16),
                 gr + (size_t)(ok ? iw : 0) * 16 + 8 + sub * 4, ok ? 16 : 0);
        }
    }
    CP_COMMIT();

    const int lane = tid & 31;
    const int wid  = tid >> 5;
    const int g = lane >> 2, t = lane & 3;
    const int orow = wid & 3;        // 0..3: output row within tile
    const int mq   = wid >> 2;       // 0..1: 64-px half

    float acc[4][4][4];
    #pragma unroll
    for (int mt = 0; mt < 4; mt++)
        #pragma unroll
        for (int nt = 0; nt < 4; nt++)
            #pragma unroll
            for (int i = 0; i < 4; i++) acc[mt][nt][i] = 0.f;

    CP_WAIT1();
    __syncthreads();
    compute_plane(sA0, sB0, acc, orow, mq, g, t);

    CP_WAIT0();
    __syncthreads();
    compute_plane(sA1, sB1, acc, orow, mq, g, t);

    // ---- epilogue (guard last y-tile: 222 % 4 != 0)
    const int oy = oh0 + orow;
    if (oy < OH_) {
        #pragma unroll
        for (int nt = 0; nt < 4; ++nt) {
            const int co0 = nt * 8 + t * 2;
            const float bs0 = __ldg(&bias[co0]);
            const float bs1 = __ldg(&bias[co0 + 1]);
            float* o0 = out + (((size_t)b * CO_ + co0)     * OH_ + oy) * OW_;
            float* o1 = out + (((size_t)b * CO_ + co0 + 1) * OH_ + oy) * OW_;
            #pragma unroll
            for (int mt = 0; mt < 4; ++mt) {
                const int pl = px0 + mq * 64 + mt * 16 + g;
                o0[pl]     = acc[mt][nt][0] + bs0;
                o1[pl]     = acc[mt][nt][1] + bs1;
                o0[pl + 8] = acc[mt][nt][2] + bs0;
                o1[pl + 8] = acc[mt][nt][3] + bs1;
            }
        }
    }
}

extern "C" void kernel_launch(void* const* d_in, const int* in_sizes, int n_in,
                              void* d_out, int out_size)
{
    const float* x    = (const float*)d_in[0];
    const float* w    = (const float*)d_in[1];
    const float* bias = (const float*)d_in[2];
    float* out        = (float*)d_out;

    cvt_xw<<<XBLOCKS + 1, 256>>>(x, w);

    cudaFuncSetAttribute(conv3x3_mma,
                         cudaFuncAttributeMaxDynamicSharedMemorySize, SMEM_BYTES);
    conv3x3_mma<<<B_ * YT * XT, THREADS, SMEM_BYTES>>>(bias, out);
}